// round 4
// baseline (speedup 1.0000x reference)
#include <cuda_runtime.h>
#include <cuda_fp16.h>

#define N_NODES 50000
#define N_EDGES 1600000
#define IN_F    256
#define OUT_F   128
#define NEG_SLOPE 0.2f

#define GEMM_BLOCKS ((N_NODES + 127) / 128)   // 391
#define HIST_BLOCKS 1024
#define SCAN_BLOCKS ((N_NODES + 1023) / 1024) // 49

// ---------------- scratch (static device globals) -------------------------
__device__ __half g_h[(size_t)N_NODES * OUT_F];   // 12.8 MB, fp16
__device__ float  g_el[N_NODES];
__device__ float  g_er[N_NODES];
__device__ int    g_deg[N_NODES];
__device__ int    g_off[N_NODES + 1];
__device__ int    g_pos[N_NODES];
__device__ float2 g_edge[N_EDGES];                // (src bits, leaky logit), dst-sorted
__device__ int    g_bsum[64];

// ---------------- packed f32x2 helpers -------------------------------------
__device__ __forceinline__ unsigned long long pack_dup(float x) {
    unsigned long long r;
    asm("mov.b64 %0, {%1, %1};" : "=l"(r) : "f"(x));
    return r;
}
__device__ __forceinline__ void fma2(unsigned long long& acc,
                                     unsigned long long a, unsigned long long b) {
    asm("fma.rn.f32x2 %0, %1, %2, %0;" : "+l"(acc) : "l"(a), "l"(b));
}
__device__ __forceinline__ float2 unpack2(unsigned long long v) {
    float2 f;
    asm("mov.b64 {%0, %1}, %2;" : "=f"(f.x), "=f"(f.y) : "l"(v));
    return f;
}

// ---------------- 1) fused: h = feat @ W^T (+el/er)  ||  dst histogram -----
__global__ __launch_bounds__(256) void gemm_hist_kernel(
        const float* __restrict__ feat,
        const float* __restrict__ W,
        const float* __restrict__ attn_l,
        const float* __restrict__ attn_r,
        const int*   __restrict__ dst) {
    // ---- trailing blocks: histogram of dst (fills gemm's wave tail) ----
    if (blockIdx.x >= GEMM_BLOCKS) {
        int bid = blockIdx.x - GEMM_BLOCKS;
        int t   = bid * blockDim.x + threadIdx.x;
        const int4* d4 = (const int4*)dst;
        const int n4 = N_EDGES / 4;                 // divisible
        for (int i = t; i < n4; i += HIST_BLOCKS * 256) {
            int4 v = d4[i];
            atomicAdd(&g_deg[v.x], 1);
            atomicAdd(&g_deg[v.y], 1);
            atomicAdd(&g_deg[v.z], 1);
            atomicAdd(&g_deg[v.w], 1);
        }
        return;
    }

    // ---- gemm blocks ----
    const int BM = 128, BK = 16;
    __shared__ float As[BK][BM];
    __shared__ float Bs[BK][BM];

    int tid  = threadIdx.x;              // 256 threads
    int row0 = blockIdx.x * BM;
    int tm   = tid >> 4;                 // 0..15
    int tn   = tid & 15;                 // 0..15

    unsigned long long acc2[8][4];
#pragma unroll
    for (int i = 0; i < 8; i++)
#pragma unroll
        for (int j = 0; j < 4; j++) acc2[i][j] = 0ull;

    int l0  = tid * 2, l1 = tid * 2 + 1;
    int ar0 = l0 >> 2, ak0 = (l0 & 3) * 4;
    int ar1 = l1 >> 2, ak1 = (l1 & 3) * 4;

    for (int kk = 0; kk < IN_F; kk += BK) {
        float4 a0 = make_float4(0.f, 0.f, 0.f, 0.f), a1 = a0;
        if (row0 + ar0 < N_NODES)
            a0 = *(const float4*)&feat[(size_t)(row0 + ar0) * IN_F + kk + ak0];
        if (row0 + ar1 < N_NODES)
            a1 = *(const float4*)&feat[(size_t)(row0 + ar1) * IN_F + kk + ak1];
        float4 b0 = *(const float4*)&W[(size_t)ar0 * IN_F + kk + ak0];
        float4 b1 = *(const float4*)&W[(size_t)ar1 * IN_F + kk + ak1];

        As[ak0 + 0][ar0] = a0.x; As[ak0 + 1][ar0] = a0.y;
        As[ak0 + 2][ar0] = a0.z; As[ak0 + 3][ar0] = a0.w;
        As[ak1 + 0][ar1] = a1.x; As[ak1 + 1][ar1] = a1.y;
        As[ak1 + 2][ar1] = a1.z; As[ak1 + 3][ar1] = a1.w;
        Bs[ak0 + 0][ar0] = b0.x; Bs[ak0 + 1][ar0] = b0.y;
        Bs[ak0 + 2][ar0] = b0.z; Bs[ak0 + 3][ar0] = b0.w;
        Bs[ak1 + 0][ar1] = b1.x; Bs[ak1 + 1][ar1] = b1.y;
        Bs[ak1 + 2][ar1] = b1.z; Bs[ak1 + 3][ar1] = b1.w;
        __syncthreads();

#pragma unroll
        for (int k = 0; k < BK; k++) {
            float4 ra0 = *(const float4*)&As[k][tm * 8 + 0];
            float4 ra1 = *(const float4*)&As[k][tm * 8 + 4];
            ulonglong2 rb0 = *(const ulonglong2*)&Bs[k][tn * 8 + 0];
            ulonglong2 rb1 = *(const ulonglong2*)&Bs[k][tn * 8 + 4];
            unsigned long long b2[4] = {rb0.x, rb0.y, rb1.x, rb1.y};
            unsigned long long a2[8];
            a2[0] = pack_dup(ra0.x); a2[1] = pack_dup(ra0.y);
            a2[2] = pack_dup(ra0.z); a2[3] = pack_dup(ra0.w);
            a2[4] = pack_dup(ra1.x); a2[5] = pack_dup(ra1.y);
            a2[6] = pack_dup(ra1.z); a2[7] = pack_dup(ra1.w);
#pragma unroll
            for (int i = 0; i < 8; i++)
#pragma unroll
                for (int j = 0; j < 4; j++) fma2(acc2[i][j], a2[i], b2[j]);
        }
        __syncthreads();
    }

    float al[8], ar[8];
    {
        float4 t0 = *(const float4*)&attn_l[tn * 8 + 0];
        float4 t1 = *(const float4*)&attn_l[tn * 8 + 4];
        al[0]=t0.x; al[1]=t0.y; al[2]=t0.z; al[3]=t0.w;
        al[4]=t1.x; al[5]=t1.y; al[6]=t1.z; al[7]=t1.w;
        float4 u0 = *(const float4*)&attn_r[tn * 8 + 0];
        float4 u1 = *(const float4*)&attn_r[tn * 8 + 4];
        ar[0]=u0.x; ar[1]=u0.y; ar[2]=u0.z; ar[3]=u0.w;
        ar[4]=u1.x; ar[5]=u1.y; ar[6]=u1.z; ar[7]=u1.w;
    }

#pragma unroll
    for (int i = 0; i < 8; i++) {
        float c[8];
#pragma unroll
        for (int j = 0; j < 4; j++) {
            float2 f = unpack2(acc2[i][j]);
            c[2 * j] = f.x; c[2 * j + 1] = f.y;
        }
        int n = row0 + tm * 8 + i;
        if (n < N_NODES) {
            // pack 8 fp32 -> 8 fp16 (one 16B store)
            __half2 p0 = __floats2half2_rn(c[0], c[1]);
            __half2 p1 = __floats2half2_rn(c[2], c[3]);
            __half2 p2 = __floats2half2_rn(c[4], c[5]);
            __half2 p3 = __floats2half2_rn(c[6], c[7]);
            uint4 pk;
            pk.x = *(unsigned*)&p0; pk.y = *(unsigned*)&p1;
            pk.z = *(unsigned*)&p2; pk.w = *(unsigned*)&p3;
            *(uint4*)&g_h[(size_t)n * OUT_F + tn * 8] = pk;
        }
        float pl = 0.f, pr = 0.f;
#pragma unroll
        for (int j = 0; j < 8; j++) { pl += c[j] * al[j]; pr += c[j] * ar[j]; }
#pragma unroll
        for (int d = 1; d < 16; d <<= 1) {
            pl += __shfl_xor_sync(0xffffffffu, pl, d);
            pr += __shfl_xor_sync(0xffffffffu, pr, d);
        }
        if (tn == 0 && n < N_NODES) { g_el[n] = pl; g_er[n] = pr; }
    }
}

// ---------------- 2) scan stage 1: per-1024-block sums ---------------------
__global__ __launch_bounds__(1024) void scan1_kernel() {
    __shared__ int ws[32];
    int tid = threadIdx.x, lane = tid & 31, warp = tid >> 5;
    int idx = blockIdx.x * 1024 + tid;
    int v = (idx < N_NODES) ? g_deg[idx] : 0;
    int s = v;
#pragma unroll
    for (int d = 16; d; d >>= 1) s += __shfl_xor_sync(0xffffffffu, s, d);
    if (lane == 0) ws[warp] = s;
    __syncthreads();
    if (warp == 0) {
        int t = ws[lane];
#pragma unroll
        for (int d = 16; d; d >>= 1) t += __shfl_xor_sync(0xffffffffu, t, d);
        if (lane == 0) g_bsum[blockIdx.x] = t;
    }
}

// ---------------- scan stages 2+3 merged ------------------------------------
__global__ __launch_bounds__(1024) void scan23_kernel() {
    __shared__ int ws[32];
    __shared__ int blk_pref[64];
    int tid = threadIdx.x, lane = tid & 31, warp = tid >> 5;

    if (warp < 2) {
        int i = tid;                       // 0..63
        int v = (i < SCAN_BLOCKS) ? g_bsum[i] : 0;
        int incl = v;
#pragma unroll
        for (int d = 1; d < 32; d <<= 1) {
            int t = __shfl_up_sync(0xffffffffu, incl, d);
            if (lane >= d) incl += t;
        }
        blk_pref[i] = incl - v;
    }
    __syncthreads();
    if (tid == 32) {
        int w0 = blk_pref[31] + g_bsum[31];
        for (int i = 32; i < 64; i++) blk_pref[i] += w0;
    }
    __syncthreads();

    int idx = blockIdx.x * 1024 + tid;
    int v = (idx < N_NODES) ? g_deg[idx] : 0;
    int incl = v;
#pragma unroll
    for (int d = 1; d < 32; d <<= 1) {
        int t = __shfl_up_sync(0xffffffffu, incl, d);
        if (lane >= d) incl += t;
    }
    if (lane == 31) ws[warp] = incl;
    __syncthreads();
    if (warp == 0) {
        int t = ws[lane];
#pragma unroll
        for (int d = 1; d < 32; d <<= 1) {
            int u = __shfl_up_sync(0xffffffffu, t, d);
            if (lane >= d) t += u;
        }
        ws[lane] = t;
    }
    __syncthreads();
    int excl = blk_pref[blockIdx.x] + ((warp > 0) ? ws[warp - 1] : 0) + incl - v;
    if (idx < N_NODES) { g_off[idx] = excl; g_pos[idx] = excl; }
    if (idx == N_NODES - 1) g_off[N_NODES] = N_EDGES;
}

// ---------------- 3) scatter (src, leaky logit) into dst-sorted order ------
__global__ void scatter_kernel(const int* __restrict__ src,
                               const int* __restrict__ dst) {
    int i = blockIdx.x * blockDim.x + threadIdx.x;
    const int n4 = N_EDGES / 4;
    if (i >= n4) return;
    int4 s4 = ((const int4*)src)[i];
    int4 d4 = ((const int4*)dst)[i];
#pragma unroll
    for (int q = 0; q < 4; q++) {
        int s = (q == 0) ? s4.x : (q == 1) ? s4.y : (q == 2) ? s4.z : s4.w;
        int d = (q == 0) ? d4.x : (q == 1) ? d4.y : (q == 2) ? d4.z : d4.w;
        float e = g_el[s] + g_er[d];
        e = (e > 0.f) ? e : NEG_SLOPE * e;
        int p = atomicAdd(&g_pos[d], 1);
        g_edge[p] = make_float2(__int_as_float(s), e);
    }
}

// ---------------- 4) softmax + aggregation, one warp per dst node ----------
__global__ void agg_kernel(float* __restrict__ out) {
    int w    = (blockIdx.x * blockDim.x + threadIdx.x) >> 5;
    int lane = threadIdx.x & 31;
    if (w >= N_NODES) return;

    int beg = g_off[w], end = g_off[w + 1];

    // online softmax stats over coalesced logit sweep
    float m = -3.402823466e38f, s = 0.f;
    for (int i = beg + lane; i < end; i += 32) {
        float e = g_edge[i].y;
        float mn = fmaxf(m, e);
        s = s * __expf(m - mn) + __expf(e - mn);
        m = mn;
    }
#pragma unroll
    for (int d = 16; d; d >>= 1) {
        float m2 = __shfl_xor_sync(0xffffffffu, m, d);
        float s2 = __shfl_xor_sync(0xffffffffu, s, d);
        float mn = fmaxf(m, m2);
        s = s * __expf(m - mn) + s2 * __expf(m2 - mn);
        m = mn;
    }
    float inv = 1.f / fmaxf(s, 1e-9f);

    // acc = sum alpha_e * h[src_e]; each lane owns 4 features (8 B fp16 gather)
    float4 acc = make_float4(0.f, 0.f, 0.f, 0.f);
    for (int j0 = beg; j0 < end; j0 += 32) {
        int myj = j0 + lane;
        int sidx = 0; float a = 0.f;
        if (myj < end) {
            float2 ed = g_edge[myj];
            sidx = __float_as_int(ed.x);
            a = __expf(ed.y - m) * inv;
        }
        int cnt = min(32, end - j0);
        for (int t = 0; t < cnt; t++) {
            int   ss = __shfl_sync(0xffffffffu, sidx, t);
            float aa = __shfl_sync(0xffffffffu, a, t);
            uint2 u = *(const uint2*)&g_h[(size_t)ss * OUT_F + lane * 4];
            __half2 h0 = *(__half2*)&u.x;
            __half2 h1 = *(__half2*)&u.y;
            float2 f0 = __half22float2(h0);
            float2 f1 = __half22float2(h1);
            acc.x += aa * f0.x; acc.y += aa * f0.y;
            acc.z += aa * f1.x; acc.w += aa * f1.y;
        }
    }
    *(float4*)&out[(size_t)w * OUT_F + lane * 4] = acc;
}

// ---------------- launch ----------------------------------------------------
extern "C" void kernel_launch(void* const* d_in, const int* in_sizes, int n_in,
                              void* d_out, int out_size) {
    const float* feat   = (const float*)d_in[0];
    const float* W      = (const float*)d_in[1];
    const float* attn_l = (const float*)d_in[2];
    const float* attn_r = (const float*)d_in[3];
    const int*   src    = (const int*)d_in[4];
    const int*   dst    = (const int*)d_in[5];
    float* out = (float*)d_out;

    void* deg_ptr = nullptr;
    cudaGetSymbolAddress(&deg_ptr, g_deg);
    cudaMemsetAsync(deg_ptr, 0, N_NODES * sizeof(int));

    gemm_hist_kernel<<<GEMM_BLOCKS + HIST_BLOCKS, 256>>>(feat, W, attn_l, attn_r, dst);
    scan1_kernel<<<SCAN_BLOCKS, 1024>>>();
    scan23_kernel<<<SCAN_BLOCKS, 1024>>>();
    scatter_kernel<<<(N_EDGES / 4 + 255) / 256, 256>>>(src, dst);
    agg_kernel<<<(N_NODES * 32 + 255) / 256, 256>>>(out);
}

// round 5
// speedup vs baseline: 1.0043x; 1.0043x over previous
#include <cuda_runtime.h>
#include <cuda_fp16.h>

#define N_NODES 50000
#define N_EDGES 1600000
#define IN_F    256
#define OUT_F   128
#define NEG_SLOPE 0.2f

#define GEMM_BLOCKS ((N_NODES + 127) / 128)   // 391
#define HIST_BLOCKS 1024
#define SCAN_BLOCKS ((N_NODES + 1023) / 1024) // 49

// ---------------- scratch (static device globals) -------------------------
__device__ __half g_h[(size_t)N_NODES * OUT_F];   // 12.8 MB, fp16
__device__ float  g_el[N_NODES];
__device__ float  g_er[N_NODES];
__device__ int    g_deg[N_NODES];
__device__ int    g_off[N_NODES + 1];
__device__ int    g_rank[N_EDGES];                // per-edge arrival rank within dst
__device__ float2 g_edge[N_EDGES];                // (src bits, leaky logit), dst-sorted
__device__ int    g_bsum[64];

// ---------------- packed f32x2 helpers -------------------------------------
__device__ __forceinline__ unsigned long long pack_dup(float x) {
    unsigned long long r;
    asm("mov.b64 %0, {%1, %1};" : "=l"(r) : "f"(x));
    return r;
}
__device__ __forceinline__ void fma2(unsigned long long& acc,
                                     unsigned long long a, unsigned long long b) {
    asm("fma.rn.f32x2 %0, %1, %2, %0;" : "+l"(acc) : "l"(a), "l"(b));
}
__device__ __forceinline__ float2 unpack2(unsigned long long v) {
    float2 f;
    asm("mov.b64 {%0, %1}, %2;" : "=f"(f.x), "=f"(f.y) : "l"(v));
    return f;
}

// ---------------- 1) fused: h = feat @ W^T (+el/er)  ||  hist+rank ---------
__global__ __launch_bounds__(256) void gemm_hist_kernel(
        const float* __restrict__ feat,
        const float* __restrict__ W,
        const float* __restrict__ attn_l,
        const float* __restrict__ attn_r,
        const int*   __restrict__ dst) {
    // ---- trailing blocks: histogram of dst + per-edge rank ----
    if (blockIdx.x >= GEMM_BLOCKS) {
        int bid = blockIdx.x - GEMM_BLOCKS;
        int t   = bid * blockDim.x + threadIdx.x;
        const int4* d4 = (const int4*)dst;
        int4* r4 = (int4*)g_rank;
        const int n4 = N_EDGES / 4;                 // divisible
        for (int i = t; i < n4; i += HIST_BLOCKS * 256) {
            int4 v = d4[i];
            int4 r;
            r.x = atomicAdd(&g_deg[v.x], 1);
            r.y = atomicAdd(&g_deg[v.y], 1);
            r.z = atomicAdd(&g_deg[v.z], 1);
            r.w = atomicAdd(&g_deg[v.w], 1);
            r4[i] = r;
        }
        return;
    }

    // ---- gemm blocks ----
    const int BM = 128, BK = 16;
    __shared__ float As[BK][BM];
    __shared__ float Bs[BK][BM];

    int tid  = threadIdx.x;              // 256 threads
    int row0 = blockIdx.x * BM;
    int tm   = tid >> 4;                 // 0..15
    int tn   = tid & 15;                 // 0..15

    unsigned long long acc2[8][4];
#pragma unroll
    for (int i = 0; i < 8; i++)
#pragma unroll
        for (int j = 0; j < 4; j++) acc2[i][j] = 0ull;

    int l0  = tid * 2, l1 = tid * 2 + 1;
    int ar0 = l0 >> 2, ak0 = (l0 & 3) * 4;
    int ar1 = l1 >> 2, ak1 = (l1 & 3) * 4;

    for (int kk = 0; kk < IN_F; kk += BK) {
        float4 a0 = make_float4(0.f, 0.f, 0.f, 0.f), a1 = a0;
        if (row0 + ar0 < N_NODES)
            a0 = *(const float4*)&feat[(size_t)(row0 + ar0) * IN_F + kk + ak0];
        if (row0 + ar1 < N_NODES)
            a1 = *(const float4*)&feat[(size_t)(row0 + ar1) * IN_F + kk + ak1];
        float4 b0 = *(const float4*)&W[(size_t)ar0 * IN_F + kk + ak0];
        float4 b1 = *(const float4*)&W[(size_t)ar1 * IN_F + kk + ak1];

        As[ak0 + 0][ar0] = a0.x; As[ak0 + 1][ar0] = a0.y;
        As[ak0 + 2][ar0] = a0.z; As[ak0 + 3][ar0] = a0.w;
        As[ak1 + 0][ar1] = a1.x; As[ak1 + 1][ar1] = a1.y;
        As[ak1 + 2][ar1] = a1.z; As[ak1 + 3][ar1] = a1.w;
        Bs[ak0 + 0][ar0] = b0.x; Bs[ak0 + 1][ar0] = b0.y;
        Bs[ak0 + 2][ar0] = b0.z; Bs[ak0 + 3][ar0] = b0.w;
        Bs[ak1 + 0][ar1] = b1.x; Bs[ak1 + 1][ar1] = b1.y;
        Bs[ak1 + 2][ar1] = b1.z; Bs[ak1 + 3][ar1] = b1.w;
        __syncthreads();

#pragma unroll
        for (int k = 0; k < BK; k++) {
            float4 ra0 = *(const float4*)&As[k][tm * 8 + 0];
            float4 ra1 = *(const float4*)&As[k][tm * 8 + 4];
            ulonglong2 rb0 = *(const ulonglong2*)&Bs[k][tn * 8 + 0];
            ulonglong2 rb1 = *(const ulonglong2*)&Bs[k][tn * 8 + 4];
            unsigned long long b2[4] = {rb0.x, rb0.y, rb1.x, rb1.y};
            unsigned long long a2[8];
            a2[0] = pack_dup(ra0.x); a2[1] = pack_dup(ra0.y);
            a2[2] = pack_dup(ra0.z); a2[3] = pack_dup(ra0.w);
            a2[4] = pack_dup(ra1.x); a2[5] = pack_dup(ra1.y);
            a2[6] = pack_dup(ra1.z); a2[7] = pack_dup(ra1.w);
#pragma unroll
            for (int i = 0; i < 8; i++)
#pragma unroll
                for (int j = 0; j < 4; j++) fma2(acc2[i][j], a2[i], b2[j]);
        }
        __syncthreads();
    }

    float al[8], ar[8];
    {
        float4 t0 = *(const float4*)&attn_l[tn * 8 + 0];
        float4 t1 = *(const float4*)&attn_l[tn * 8 + 4];
        al[0]=t0.x; al[1]=t0.y; al[2]=t0.z; al[3]=t0.w;
        al[4]=t1.x; al[5]=t1.y; al[6]=t1.z; al[7]=t1.w;
        float4 u0 = *(const float4*)&attn_r[tn * 8 + 0];
        float4 u1 = *(const float4*)&attn_r[tn * 8 + 4];
        ar[0]=u0.x; ar[1]=u0.y; ar[2]=u0.z; ar[3]=u0.w;
        ar[4]=u1.x; ar[5]=u1.y; ar[6]=u1.z; ar[7]=u1.w;
    }

#pragma unroll
    for (int i = 0; i < 8; i++) {
        float c[8];
#pragma unroll
        for (int j = 0; j < 4; j++) {
            float2 f = unpack2(acc2[i][j]);
            c[2 * j] = f.x; c[2 * j + 1] = f.y;
        }
        int n = row0 + tm * 8 + i;
        if (n < N_NODES) {
            __half2 p0 = __floats2half2_rn(c[0], c[1]);
            __half2 p1 = __floats2half2_rn(c[2], c[3]);
            __half2 p2 = __floats2half2_rn(c[4], c[5]);
            __half2 p3 = __floats2half2_rn(c[6], c[7]);
            uint4 pk;
            pk.x = *(unsigned*)&p0; pk.y = *(unsigned*)&p1;
            pk.z = *(unsigned*)&p2; pk.w = *(unsigned*)&p3;
            *(uint4*)&g_h[(size_t)n * OUT_F + tn * 8] = pk;
        }
        float pl = 0.f, pr = 0.f;
#pragma unroll
        for (int j = 0; j < 8; j++) { pl += c[j] * al[j]; pr += c[j] * ar[j]; }
#pragma unroll
        for (int d = 1; d < 16; d <<= 1) {
            pl += __shfl_xor_sync(0xffffffffu, pl, d);
            pr += __shfl_xor_sync(0xffffffffu, pr, d);
        }
        if (tn == 0 && n < N_NODES) { g_el[n] = pl; g_er[n] = pr; }
    }
}

// ---------------- 2) scan stage 1: per-1024-block sums ---------------------
__global__ __launch_bounds__(1024) void scan1_kernel() {
    __shared__ int ws[32];
    int tid = threadIdx.x, lane = tid & 31, warp = tid >> 5;
    int idx = blockIdx.x * 1024 + tid;
    int v = (idx < N_NODES) ? g_deg[idx] : 0;
    int s = v;
#pragma unroll
    for (int d = 16; d; d >>= 1) s += __shfl_xor_sync(0xffffffffu, s, d);
    if (lane == 0) ws[warp] = s;
    __syncthreads();
    if (warp == 0) {
        int t = ws[lane];
#pragma unroll
        for (int d = 16; d; d >>= 1) t += __shfl_xor_sync(0xffffffffu, t, d);
        if (lane == 0) g_bsum[blockIdx.x] = t;
    }
}

// ---------------- scan stages 2+3 merged ------------------------------------
__global__ __launch_bounds__(1024) void scan23_kernel() {
    __shared__ int ws[32];
    __shared__ int blk_pref[64];
    int tid = threadIdx.x, lane = tid & 31, warp = tid >> 5;

    if (warp < 2) {
        int i = tid;                       // 0..63
        int v = (i < SCAN_BLOCKS) ? g_bsum[i] : 0;
        int incl = v;
#pragma unroll
        for (int d = 1; d < 32; d <<= 1) {
            int t = __shfl_up_sync(0xffffffffu, incl, d);
            if (lane >= d) incl += t;
        }
        blk_pref[i] = incl - v;
    }
    __syncthreads();
    if (tid == 32) {
        int w0 = blk_pref[31] + g_bsum[31];
        for (int i = 32; i < 64; i++) blk_pref[i] += w0;
    }
    __syncthreads();

    int idx = blockIdx.x * 1024 + tid;
    int v = (idx < N_NODES) ? g_deg[idx] : 0;
    int incl = v;
#pragma unroll
    for (int d = 1; d < 32; d <<= 1) {
        int t = __shfl_up_sync(0xffffffffu, incl, d);
        if (lane >= d) incl += t;
    }
    if (lane == 31) ws[warp] = incl;
    __syncthreads();
    if (warp == 0) {
        int t = ws[lane];
#pragma unroll
        for (int d = 1; d < 32; d <<= 1) {
            int u = __shfl_up_sync(0xffffffffu, t, d);
            if (lane >= d) t += u;
        }
        ws[lane] = t;
    }
    __syncthreads();
    int excl = blk_pref[blockIdx.x] + ((warp > 0) ? ws[warp - 1] : 0) + incl - v;
    if (idx < N_NODES) g_off[idx] = excl;
    if (idx == N_NODES - 1) g_off[N_NODES] = N_EDGES;
}

// ---------------- 3) scatter (src, leaky logit), atomic-free ----------------
__global__ void scatter_kernel(const int* __restrict__ src,
                               const int* __restrict__ dst) {
    int i = blockIdx.x * blockDim.x + threadIdx.x;
    const int n4 = N_EDGES / 4;
    if (i >= n4) return;
    int4 s4 = ((const int4*)src)[i];
    int4 d4 = ((const int4*)dst)[i];
    int4 r4 = ((const int4*)g_rank)[i];
#pragma unroll
    for (int q = 0; q < 4; q++) {
        int s = (q == 0) ? s4.x : (q == 1) ? s4.y : (q == 2) ? s4.z : s4.w;
        int d = (q == 0) ? d4.x : (q == 1) ? d4.y : (q == 2) ? d4.z : d4.w;
        int r = (q == 0) ? r4.x : (q == 1) ? r4.y : (q == 2) ? r4.z : r4.w;
        float e = g_el[s] + g_er[d];
        e = (e > 0.f) ? e : NEG_SLOPE * e;
        g_edge[g_off[d] + r] = make_float2(__int_as_float(s), e);
    }
}

// ---------------- 4) softmax + aggregation, one warp per dst node ----------
__device__ __forceinline__ void fma_h(float4& acc, float aa, unsigned ss, int lane) {
    uint2 u = *(const uint2*)&g_h[(size_t)ss * OUT_F + lane * 4];
    float2 f0 = __half22float2(*(__half2*)&u.x);
    float2 f1 = __half22float2(*(__half2*)&u.y);
    acc.x += aa * f0.x; acc.y += aa * f0.y;
    acc.z += aa * f1.x; acc.w += aa * f1.y;
}

__global__ void agg_kernel(float* __restrict__ out) {
    int w    = (blockIdx.x * blockDim.x + threadIdx.x) >> 5;
    int lane = threadIdx.x & 31;
    if (w >= N_NODES) return;

    int beg = g_off[w], end = g_off[w + 1];

    // online softmax stats over coalesced logit sweep
    float m = -3.402823466e38f, s = 0.f;
    for (int i = beg + lane; i < end; i += 32) {
        float e = g_edge[i].y;
        float mn = fmaxf(m, e);
        s = s * __expf(m - mn) + __expf(e - mn);
        m = mn;
    }
#pragma unroll
    for (int d = 16; d; d >>= 1) {
        float m2 = __shfl_xor_sync(0xffffffffu, m, d);
        float s2 = __shfl_xor_sync(0xffffffffu, s, d);
        float mn = fmaxf(m, m2);
        s = s * __expf(m - mn) + s2 * __expf(m2 - mn);
        m = mn;
    }
    float inv = 1.f / fmaxf(s, 1e-9f);

    // acc = sum alpha_e * h[src_e]; 4-way unrolled independent gathers (MLP>=4)
    float4 acc = make_float4(0.f, 0.f, 0.f, 0.f);
    for (int j0 = beg; j0 < end; j0 += 32) {
        int myj = j0 + lane;
        int sidx = 0; float a = 0.f;
        if (myj < end) {
            float2 ed = g_edge[myj];
            sidx = __float_as_int(ed.x);
            a = __expf(ed.y - m) * inv;
        }
        int cnt = min(32, end - j0);
        int t = 0;
        for (; t + 4 <= cnt; t += 4) {
            int   ss0 = __shfl_sync(0xffffffffu, sidx, t + 0);
            int   ss1 = __shfl_sync(0xffffffffu, sidx, t + 1);
            int   ss2 = __shfl_sync(0xffffffffu, sidx, t + 2);
            int   ss3 = __shfl_sync(0xffffffffu, sidx, t + 3);
            float a0 = __shfl_sync(0xffffffffu, a, t + 0);
            float a1 = __shfl_sync(0xffffffffu, a, t + 1);
            float a2 = __shfl_sync(0xffffffffu, a, t + 2);
            float a3 = __shfl_sync(0xffffffffu, a, t + 3);
            // 4 independent gathers issued back-to-back
            uint2 u0 = *(const uint2*)&g_h[(size_t)ss0 * OUT_F + lane * 4];
            uint2 u1 = *(const uint2*)&g_h[(size_t)ss1 * OUT_F + lane * 4];
            uint2 u2 = *(const uint2*)&g_h[(size_t)ss2 * OUT_F + lane * 4];
            uint2 u3 = *(const uint2*)&g_h[(size_t)ss3 * OUT_F + lane * 4];
            float2 f;
            f = __half22float2(*(__half2*)&u0.x); acc.x += a0 * f.x; acc.y += a0 * f.y;
            f = __half22float2(*(__half2*)&u0.y); acc.z += a0 * f.x; acc.w += a0 * f.y;
            f = __half22float2(*(__half2*)&u1.x); acc.x += a1 * f.x; acc.y += a1 * f.y;
            f = __half22float2(*(__half2*)&u1.y); acc.z += a1 * f.x; acc.w += a1 * f.y;
            f = __half22float2(*(__half2*)&u2.x); acc.x += a2 * f.x; acc.y += a2 * f.y;
            f = __half22float2(*(__half2*)&u2.y); acc.z += a2 * f.x; acc.w += a2 * f.y;
            f = __half22float2(*(__half2*)&u3.x); acc.x += a3 * f.x; acc.y += a3 * f.y;
            f = __half22float2(*(__half2*)&u3.y); acc.z += a3 * f.x; acc.w += a3 * f.y;
        }
        for (; t < cnt; t++) {
            int   ss = __shfl_sync(0xffffffffu, sidx, t);
            float aa = __shfl_sync(0xffffffffu, a, t);
            fma_h(acc, aa, ss, lane);
        }
    }
    *(float4*)&out[(size_t)w * OUT_F + lane * 4] = acc;
}

// ---------------- launch ----------------------------------------------------
extern "C" void kernel_launch(void* const* d_in, const int* in_sizes, int n_in,
                              void* d_out, int out_size) {
    const float* feat   = (const float*)d_in[0];
    const float* W      = (const float*)d_in[1];
    const float* attn_l = (const float*)d_in[2];
    const float* attn_r = (const float*)d_in[3];
    const int*   src    = (const int*)d_in[4];
    const int*   dst    = (const int*)d_in[5];
    float* out = (float*)d_out;

    void* deg_ptr = nullptr;
    cudaGetSymbolAddress(&deg_ptr, g_deg);
    cudaMemsetAsync(deg_ptr, 0, N_NODES * sizeof(int));

    gemm_hist_kernel<<<GEMM_BLOCKS + HIST_BLOCKS, 256>>>(feat, W, attn_l, attn_r, dst);
    scan1_kernel<<<SCAN_BLOCKS, 1024>>>();
    scan23_kernel<<<SCAN_BLOCKS, 1024>>>();
    scatter_kernel<<<(N_EDGES / 4 + 255) / 256, 256>>>(src, dst);
    agg_kernel<<<(N_NODES * 32 + 255) / 256, 256>>>(out);
}

// round 7
// speedup vs baseline: 1.0581x; 1.0536x over previous
#include <cuda_runtime.h>
#include <cuda_fp16.h>

#define N_NODES 50000
#define N_EDGES 1600000
#define IN_F    256
#define OUT_F   128
#define NEG_SLOPE 0.2f

#define GEMM_BLOCKS ((N_NODES + 127) / 128)   // 391
#define SCAN_BLOCKS ((N_NODES + 1023) / 1024) // 49

// ---------------- scratch (static device globals) -------------------------
__device__ __half g_h[(size_t)N_NODES * OUT_F];   // 12.8 MB, fp16
__device__ float  g_el[N_NODES];
__device__ float  g_er[N_NODES];
__device__ int    g_deg[N_NODES];
__device__ int    g_off[N_NODES + 1];
__device__ int    g_rank[N_EDGES];
__device__ float2 g_edge[N_EDGES];                // (src bits, raw el[src]), dst-sorted
__device__ int    g_bsum[64];

// ---------------- packed f32x2 helpers -------------------------------------
__device__ __forceinline__ unsigned long long pack_dup(float x) {
    unsigned long long r;
    asm("mov.b64 %0, {%1, %1};" : "=l"(r) : "f"(x));
    return r;
}
__device__ __forceinline__ void fma2(unsigned long long& acc,
                                     unsigned long long a, unsigned long long b) {
    asm("fma.rn.f32x2 %0, %1, %2, %0;" : "+l"(acc) : "l"(a), "l"(b));
}
__device__ __forceinline__ float2 unpack2(unsigned long long v) {
    float2 f;
    asm("mov.b64 {%0, %1}, %2;" : "=f"(f.x), "=f"(f.y) : "l"(v));
    return f;
}

// ---------------- 1a) gemm: h = feat @ W^T (+fused el/er) ------------------
__global__ __launch_bounds__(256) void gemm_kernel(
        const float* __restrict__ feat,
        const float* __restrict__ W,
        const float* __restrict__ attn_l,
        const float* __restrict__ attn_r) {
    const int BM = 128, BK = 16;
    __shared__ float As[BK][BM];
    __shared__ float Bs[BK][BM];

    int tid  = threadIdx.x;              // 256 threads
    int row0 = blockIdx.x * BM;
    int tm   = tid >> 4;                 // 0..15
    int tn   = tid & 15;                 // 0..15

    unsigned long long acc2[8][4];
#pragma unroll
    for (int i = 0; i < 8; i++)
#pragma unroll
        for (int j = 0; j < 4; j++) acc2[i][j] = 0ull;

    int l0  = tid * 2, l1 = tid * 2 + 1;
    int ar0 = l0 >> 2, ak0 = (l0 & 3) * 4;
    int ar1 = l1 >> 2, ak1 = (l1 & 3) * 4;

    for (int kk = 0; kk < IN_F; kk += BK) {
        float4 a0 = make_float4(0.f, 0.f, 0.f, 0.f), a1 = a0;
        if (row0 + ar0 < N_NODES)
            a0 = *(const float4*)&feat[(size_t)(row0 + ar0) * IN_F + kk + ak0];
        if (row0 + ar1 < N_NODES)
            a1 = *(const float4*)&feat[(size_t)(row0 + ar1) * IN_F + kk + ak1];
        float4 b0 = *(const float4*)&W[(size_t)ar0 * IN_F + kk + ak0];
        float4 b1 = *(const float4*)&W[(size_t)ar1 * IN_F + kk + ak1];

        As[ak0 + 0][ar0] = a0.x; As[ak0 + 1][ar0] = a0.y;
        As[ak0 + 2][ar0] = a0.z; As[ak0 + 3][ar0] = a0.w;
        As[ak1 + 0][ar1] = a1.x; As[ak1 + 1][ar1] = a1.y;
        As[ak1 + 2][ar1] = a1.z; As[ak1 + 3][ar1] = a1.w;
        Bs[ak0 + 0][ar0] = b0.x; Bs[ak0 + 1][ar0] = b0.y;
        Bs[ak0 + 2][ar0] = b0.z; Bs[ak0 + 3][ar0] = b0.w;
        Bs[ak1 + 0][ar1] = b1.x; Bs[ak1 + 1][ar1] = b1.y;
        Bs[ak1 + 2][ar1] = b1.z; Bs[ak1 + 3][ar1] = b1.w;
        __syncthreads();

#pragma unroll
        for (int k = 0; k < BK; k++) {
            float4 ra0 = *(const float4*)&As[k][tm * 8 + 0];
            float4 ra1 = *(const float4*)&As[k][tm * 8 + 4];
            ulonglong2 rb0 = *(const ulonglong2*)&Bs[k][tn * 8 + 0];
            ulonglong2 rb1 = *(const ulonglong2*)&Bs[k][tn * 8 + 4];
            unsigned long long b2[4] = {rb0.x, rb0.y, rb1.x, rb1.y};
            unsigned long long a2[8];
            a2[0] = pack_dup(ra0.x); a2[1] = pack_dup(ra0.y);
            a2[2] = pack_dup(ra0.z); a2[3] = pack_dup(ra0.w);
            a2[4] = pack_dup(ra1.x); a2[5] = pack_dup(ra1.y);
            a2[6] = pack_dup(ra1.z); a2[7] = pack_dup(ra1.w);
#pragma unroll
            for (int i = 0; i < 8; i++)
#pragma unroll
                for (int j = 0; j < 4; j++) fma2(acc2[i][j], a2[i], b2[j]);
        }
        __syncthreads();
    }

    float al[8], ar[8];
    {
        float4 t0 = *(const float4*)&attn_l[tn * 8 + 0];
        float4 t1 = *(const float4*)&attn_l[tn * 8 + 4];
        al[0]=t0.x; al[1]=t0.y; al[2]=t0.z; al[3]=t0.w;
        al[4]=t1.x; al[5]=t1.y; al[6]=t1.z; al[7]=t1.w;
        float4 u0 = *(const float4*)&attn_r[tn * 8 + 0];
        float4 u1 = *(const float4*)&attn_r[tn * 8 + 4];
        ar[0]=u0.x; ar[1]=u0.y; ar[2]=u0.z; ar[3]=u0.w;
        ar[4]=u1.x; ar[5]=u1.y; ar[6]=u1.z; ar[7]=u1.w;
    }

#pragma unroll
    for (int i = 0; i < 8; i++) {
        float c[8];
#pragma unroll
        for (int j = 0; j < 4; j++) {
            float2 f = unpack2(acc2[i][j]);
            c[2 * j] = f.x; c[2 * j + 1] = f.y;
        }
        int n = row0 + tm * 8 + i;
        if (n < N_NODES) {
            __half2 p0 = __floats2half2_rn(c[0], c[1]);
            __half2 p1 = __floats2half2_rn(c[2], c[3]);
            __half2 p2 = __floats2half2_rn(c[4], c[5]);
            __half2 p3 = __floats2half2_rn(c[6], c[7]);
            uint4 pk;
            pk.x = *(unsigned*)&p0; pk.y = *(unsigned*)&p1;
            pk.z = *(unsigned*)&p2; pk.w = *(unsigned*)&p3;
            *(uint4*)&g_h[(size_t)n * OUT_F + tn * 8] = pk;
        }
        float pl = 0.f, pr = 0.f;
#pragma unroll
        for (int j = 0; j < 8; j++) { pl += c[j] * al[j]; pr += c[j] * ar[j]; }
#pragma unroll
        for (int d = 1; d < 16; d <<= 1) {
            pl += __shfl_xor_sync(0xffffffffu, pl, d);
            pr += __shfl_xor_sync(0xffffffffu, pr, d);
        }
        if (tn == 0 && n < N_NODES) { g_el[n] = pl; g_er[n] = pr; }
    }
}

// ---------------- 1b) hist: dst histogram + per-edge rank (stream B) -------
__global__ void hist_kernel(const int* __restrict__ dst) {
    int i = blockIdx.x * blockDim.x + threadIdx.x;
    const int n4 = N_EDGES / 4;
    if (i >= n4) return;
    int4 v = ((const int4*)dst)[i];
    int4 r;
    r.x = atomicAdd(&g_deg[v.x], 1);
    r.y = atomicAdd(&g_deg[v.y], 1);
    r.z = atomicAdd(&g_deg[v.z], 1);
    r.w = atomicAdd(&g_deg[v.w], 1);
    ((int4*)g_rank)[i] = r;
}

// ---------------- 2) scan stage 1: per-1024-block sums ---------------------
__global__ __launch_bounds__(1024) void scan1_kernel() {
    __shared__ int ws[32];
    int tid = threadIdx.x, lane = tid & 31, warp = tid >> 5;
    int idx = blockIdx.x * 1024 + tid;
    int v = (idx < N_NODES) ? g_deg[idx] : 0;
    int s = v;
#pragma unroll
    for (int d = 16; d; d >>= 1) s += __shfl_xor_sync(0xffffffffu, s, d);
    if (lane == 0) ws[warp] = s;
    __syncthreads();
    if (warp == 0) {
        int t = ws[lane];
#pragma unroll
        for (int d = 16; d; d >>= 1) t += __shfl_xor_sync(0xffffffffu, t, d);
        if (lane == 0) g_bsum[blockIdx.x] = t;
    }
}

// ---------------- scan stages 2+3 merged ------------------------------------
__global__ __launch_bounds__(1024) void scan23_kernel() {
    __shared__ int ws[32];
    __shared__ int blk_pref[64];
    int tid = threadIdx.x, lane = tid & 31, warp = tid >> 5;

    if (warp < 2) {
        int i = tid;
        int v = (i < SCAN_BLOCKS) ? g_bsum[i] : 0;
        int incl = v;
#pragma unroll
        for (int d = 1; d < 32; d <<= 1) {
            int t = __shfl_up_sync(0xffffffffu, incl, d);
            if (lane >= d) incl += t;
        }
        blk_pref[i] = incl - v;
    }
    __syncthreads();
    if (tid == 32) {
        int w0 = blk_pref[31] + g_bsum[31];
        for (int i = 32; i < 64; i++) blk_pref[i] += w0;
    }
    __syncthreads();

    int idx = blockIdx.x * 1024 + tid;
    int v = (idx < N_NODES) ? g_deg[idx] : 0;
    int incl = v;
#pragma unroll
    for (int d = 1; d < 32; d <<= 1) {
        int t = __shfl_up_sync(0xffffffffu, incl, d);
        if (lane >= d) incl += t;
    }
    if (lane == 31) ws[warp] = incl;
    __syncthreads();
    if (warp == 0) {
        int t = ws[lane];
#pragma unroll
        for (int d = 1; d < 32; d <<= 1) {
            int u = __shfl_up_sync(0xffffffffu, t, d);
            if (lane >= d) t += u;
        }
        ws[lane] = t;
    }
    __syncthreads();
    int excl = blk_pref[blockIdx.x] + ((warp > 0) ? ws[warp - 1] : 0) + incl - v;
    if (idx < N_NODES) g_off[idx] = excl;
    if (idx == N_NODES - 1) g_off[N_NODES] = N_EDGES;
}

// ---------------- 3) scatter (src, el[src]) — no er gather ------------------
__global__ void scatter_kernel(const int* __restrict__ src,
                               const int* __restrict__ dst) {
    int i = blockIdx.x * blockDim.x + threadIdx.x;
    const int n4 = N_EDGES / 4;
    if (i >= n4) return;
    int4 s4 = ((const int4*)src)[i];
    int4 d4 = ((const int4*)dst)[i];
    int4 r4 = ((const int4*)g_rank)[i];
#pragma unroll
    for (int q = 0; q < 4; q++) {
        int s = (q == 0) ? s4.x : (q == 1) ? s4.y : (q == 2) ? s4.z : s4.w;
        int d = (q == 0) ? d4.x : (q == 1) ? d4.y : (q == 2) ? d4.z : d4.w;
        int r = (q == 0) ? r4.x : (q == 1) ? r4.y : (q == 2) ? r4.z : r4.w;
        g_edge[g_off[d] + r] = make_float2(__int_as_float(s), g_el[s]);
    }
}

// ---------------- 4) softmax + aggregation, one warp per dst node ----------
__device__ __forceinline__ void fma_h(float4& acc, float aa, unsigned ss, int lane) {
    uint2 u = *(const uint2*)&g_h[(size_t)ss * OUT_F + lane * 4];
    float2 f0 = __half22float2(*(__half2*)&u.x);
    float2 f1 = __half22float2(*(__half2*)&u.y);
    acc.x += aa * f0.x; acc.y += aa * f0.y;
    acc.z += aa * f1.x; acc.w += aa * f1.y;
}

__global__ void agg_kernel(float* __restrict__ out) {
    int w    = (blockIdx.x * blockDim.x + threadIdx.x) >> 5;
    int lane = threadIdx.x & 31;
    if (w >= N_NODES) return;

    int beg = g_off[w], end = g_off[w + 1];
    float erv = g_er[w];

    // online softmax stats; e = leaky(el_src + er_w)
    float m = -3.402823466e38f, s = 0.f;
    for (int i = beg + lane; i < end; i += 32) {
        float e = g_edge[i].y + erv;
        e = (e > 0.f) ? e : NEG_SLOPE * e;
        float mn = fmaxf(m, e);
        s = s * __expf(m - mn) + __expf(e - mn);
        m = mn;
    }
#pragma unroll
    for (int d = 16; d; d >>= 1) {
        float m2 = __shfl_xor_sync(0xffffffffu, m, d);
        float s2 = __shfl_xor_sync(0xffffffffu, s, d);
        float mn = fmaxf(m, m2);
        s = s * __expf(m - mn) + s2 * __expf(m2 - mn);
        m = mn;
    }
    float inv = 1.f / fmaxf(s, 1e-9f);

    float4 acc = make_float4(0.f, 0.f, 0.f, 0.f);
    for (int j0 = beg; j0 < end; j0 += 32) {
        int myj = j0 + lane;
        int sidx = 0; float a = 0.f;
        if (myj < end) {
            float2 ed = g_edge[myj];
            sidx = __float_as_int(ed.x);
            float e = ed.y + erv;
            e = (e > 0.f) ? e : NEG_SLOPE * e;
            a = __expf(e - m) * inv;
        }
        int cnt = min(32, end - j0);
        int t = 0;
        for (; t + 4 <= cnt; t += 4) {
            int   ss0 = __shfl_sync(0xffffffffu, sidx, t + 0);
            int   ss1 = __shfl_sync(0xffffffffu, sidx, t + 1);
            int   ss2 = __shfl_sync(0xffffffffu, sidx, t + 2);
            int   ss3 = __shfl_sync(0xffffffffu, sidx, t + 3);
            float a0 = __shfl_sync(0xffffffffu, a, t + 0);
            float a1 = __shfl_sync(0xffffffffu, a, t + 1);
            float a2 = __shfl_sync(0xffffffffu, a, t + 2);
            float a3 = __shfl_sync(0xffffffffu, a, t + 3);
            uint2 u0 = *(const uint2*)&g_h[(size_t)ss0 * OUT_F + lane * 4];
            uint2 u1 = *(const uint2*)&g_h[(size_t)ss1 * OUT_F + lane * 4];
            uint2 u2 = *(const uint2*)&g_h[(size_t)ss2 * OUT_F + lane * 4];
            uint2 u3 = *(const uint2*)&g_h[(size_t)ss3 * OUT_F + lane * 4];
            float2 f;
            f = __half22float2(*(__half2*)&u0.x); acc.x += a0 * f.x; acc.y += a0 * f.y;
            f = __half22float2(*(__half2*)&u0.y); acc.z += a0 * f.x; acc.w += a0 * f.y;
            f = __half22float2(*(__half2*)&u1.x); acc.x += a1 * f.x; acc.y += a1 * f.y;
            f = __half22float2(*(__half2*)&u1.y); acc.z += a1 * f.x; acc.w += a1 * f.y;
            f = __half22float2(*(__half2*)&u2.x); acc.x += a2 * f.x; acc.y += a2 * f.y;
            f = __half22float2(*(__half2*)&u2.y); acc.z += a2 * f.x; acc.w += a2 * f.y;
            f = __half22float2(*(__half2*)&u3.x); acc.x += a3 * f.x; acc.y += a3 * f.y;
            f = __half22float2(*(__half2*)&u3.y); acc.z += a3 * f.x; acc.w += a3 * f.y;
        }
        for (; t < cnt; t++) {
            int   ss = __shfl_sync(0xffffffffu, sidx, t);
            float aa = __shfl_sync(0xffffffffu, a, t);
            fma_h(acc, aa, ss, lane);
        }
    }
    *(float4*)&out[(size_t)w * OUT_F + lane * 4] = acc;
}

// ---------------- launch: forked-stream graph -------------------------------
extern "C" void kernel_launch(void* const* d_in, const int* in_sizes, int n_in,
                              void* d_out, int out_size) {
    const float* feat   = (const float*)d_in[0];
    const float* W      = (const float*)d_in[1];
    const float* attn_l = (const float*)d_in[2];
    const float* attn_r = (const float*)d_in[3];
    const int*   src    = (const int*)d_in[4];
    const int*   dst    = (const int*)d_in[5];
    float* out = (float*)d_out;

    // lazily-created side stream + events (host objects; first call is the
    // uncaptured correctness run, so creation happens outside capture)
    static cudaStream_t sB = nullptr;
    static cudaEvent_t evFork = nullptr, evJoin = nullptr;
    if (!sB) {
        cudaStreamCreateWithFlags(&sB, cudaStreamNonBlocking);
        cudaEventCreateWithFlags(&evFork, cudaEventDisableTiming);
        cudaEventCreateWithFlags(&evJoin, cudaEventDisableTiming);
    }

    void* deg_ptr = nullptr;
    cudaGetSymbolAddress(&deg_ptr, g_deg);

    // fork: stream B does memset -> hist -> scan1 -> scan23
    cudaEventRecord(evFork, 0);
    cudaStreamWaitEvent(sB, evFork, 0);
    cudaMemsetAsync(deg_ptr, 0, N_NODES * sizeof(int), sB);
    hist_kernel<<<(N_EDGES / 4 + 255) / 256, 256, 0, sB>>>(dst);
    scan1_kernel<<<SCAN_BLOCKS, 1024, 0, sB>>>();
    scan23_kernel<<<SCAN_BLOCKS, 1024, 0, sB>>>();
    cudaEventRecord(evJoin, sB);

    // main stream: gemm concurrently
    gemm_kernel<<<GEMM_BLOCKS, 256>>>(feat, W, attn_l, attn_r);

    // join, then scatter + agg
    cudaStreamWaitEvent(0, evJoin, 0);
    scatter_kernel<<<(N_EDGES / 4 + 255) / 256, 256>>>(src, dst);
    agg_kernel<<<(N_NODES * 32 + 255) / 256, 256>>>(out);
}